// round 2
// baseline (speedup 1.0000x reference)
#include <cuda_runtime.h>
#include <cuda_bf16.h>
#include <math.h>

// Problem constants
#define T_SEQ 4096
#define D_MODEL 2048
#define DH 128
#define NH 16
#define NKV 4
#define DKV 512   // NKV * DH

// ---------------------------------------------------------------------------
// Scratch (device globals — no allocations allowed)
// ---------------------------------------------------------------------------
__device__ float g_Q[(size_t)NH * DH * T_SEQ];   // [h][d][t]  (d-major for attention)
__device__ float g_K[(size_t)NKV * DH * T_SEQ];  // [kh][d][t]
__device__ float g_V[(size_t)T_SEQ * DKV];       // [t][kh*128+d]
__device__ float g_C[(size_t)T_SEQ * D_MODEL];   // attention context [t][h*128+d]

// ---------------------------------------------------------------------------
// SGEMM: C(MxN) = A(MxK) @ B(KxN), fp32, 128x128x8 tiles, 256 threads,
// 8x8 per-thread microtile. TC=0: row-major C. TC=1: write C^T (C[n*M+m]).
// Requires M%128==0, N%128==0, K%8==0.
// ---------------------------------------------------------------------------
template<int TC>
__global__ __launch_bounds__(256)
void sgemm128(const float* __restrict__ A, const float* __restrict__ B,
              float* __restrict__ C, int M, int N, int K)
{
    __shared__ float As[8][132];   // padded: conflict-free transpose writes
    __shared__ float Bs[8][128];

    const int tid = threadIdx.x;
    const int tx  = tid & 15;
    const int ty  = tid >> 4;
    const int m0  = blockIdx.y * 128;
    const int n0  = blockIdx.x * 128;

    const int arow = tid >> 1;           // 0..127
    const int acol = (tid & 1) << 2;     // 0 or 4
    const int brow = tid >> 5;           // 0..7
    const int bcol = (tid & 31) << 2;    // 0..124

    const float* Ap = A + (size_t)(m0 + arow) * K + acol;
    const float* Bp = B + (size_t)brow * N + n0 + bcol;

    float acc[8][8];
    #pragma unroll
    for (int i = 0; i < 8; i++)
        #pragma unroll
        for (int j = 0; j < 8; j++) acc[i][j] = 0.f;

    const int nk = K >> 3;
    for (int kt = 0; kt < nk; kt++) {
        float4 av = *(const float4*)Ap;
        float4 bv = *(const float4*)Bp;
        __syncthreads();
        As[acol + 0][arow] = av.x;
        As[acol + 1][arow] = av.y;
        As[acol + 2][arow] = av.z;
        As[acol + 3][arow] = av.w;
        *(float4*)&Bs[brow][bcol] = bv;
        __syncthreads();
        #pragma unroll
        for (int k = 0; k < 8; k++) {
            float4 a0 = *(const float4*)&As[k][ty << 2];
            float4 a1 = *(const float4*)&As[k][(ty << 2) + 64];
            float4 b0 = *(const float4*)&Bs[k][tx << 2];
            float4 b1 = *(const float4*)&Bs[k][(tx << 2) + 64];
            float ar[8] = {a0.x, a0.y, a0.z, a0.w, a1.x, a1.y, a1.z, a1.w};
            float br[8] = {b0.x, b0.y, b0.z, b0.w, b1.x, b1.y, b1.z, b1.w};
            #pragma unroll
            for (int i = 0; i < 8; i++)
                #pragma unroll
                for (int j = 0; j < 8; j++)
                    acc[i][j] = fmaf(ar[i], br[j], acc[i][j]);
        }
        Ap += 8;
        Bp += (size_t)8 * N;
    }

    #pragma unroll
    for (int hm = 0; hm < 2; hm++)
        #pragma unroll
        for (int jr = 0; jr < 4; jr++) {
            int m = m0 + hm * 64 + (ty << 2) + jr;
            #pragma unroll
            for (int hn = 0; hn < 2; hn++) {
                int n = n0 + hn * 64 + (tx << 2);
                int ai = hm * 4 + jr;
                if (TC == 0) {
                    float4 v = make_float4(acc[ai][hn*4+0], acc[ai][hn*4+1],
                                           acc[ai][hn*4+2], acc[ai][hn*4+3]);
                    *(float4*)&C[(size_t)m * N + n] = v;
                } else {
                    C[(size_t)(n + 0) * M + m] = acc[ai][hn*4+0];
                    C[(size_t)(n + 1) * M + m] = acc[ai][hn*4+1];
                    C[(size_t)(n + 2) * M + m] = acc[ai][hn*4+2];
                    C[(size_t)(n + 3) * M + m] = acc[ai][hn*4+3];
                }
            }
        }
}

// ---------------------------------------------------------------------------
// RoPE in-place on d-major Q [h][d][t] and K [kh][d][t].
// One thread per (head, freq-pair, t). Matches reference fp32 quantization:
// omega computed in double then cast to fp32; angle = fp32(t * omega).
// ---------------------------------------------------------------------------
__global__ void rope_kernel(float* __restrict__ Qd, float* __restrict__ Kd)
{
    int idx = blockIdx.x * blockDim.x + threadIdx.x;
    const int total = (NH + NKV) * (DH / 2) * T_SEQ;
    if (idx >= total) return;
    int t    = idx & (T_SEQ - 1);
    int rest = idx >> 12;                       // T_SEQ = 2^12
    float* base;
    int i;
    if (rest < NH * (DH / 2)) {
        int h = rest >> 6;  i = rest & 63;
        base = Qd + (size_t)(h * DH + 2 * i) * T_SEQ + t;
    } else {
        rest -= NH * (DH / 2);
        int h = rest >> 6;  i = rest & 63;
        base = Kd + (size_t)(h * DH + 2 * i) * T_SEQ + t;
    }
    float omega = (float)(1.0 / pow(10000.0, (double)(2 * i) / (double)DH));
    float ang = (float)t * omega;
    float s, c;
    sincosf(ang, &s, &c);
    float x0 = base[0];
    float x1 = base[T_SEQ];
    base[0]     = x0 * c - x1 * s;
    base[T_SEQ] = x0 * s + x1 * c;
}

// ---------------------------------------------------------------------------
// Flash attention, fp32, online softmax, causal, GQA (h -> h>>2).
// Block: 256 threads (16x16), q-tile 64, kv-tile 64.
// Qs/Ks stored d-major [128][68] (pad 68 keeps float4 alignment, kills
// transpose-write conflicts). Vs row-major [64][128]. P staged transposed.
// ---------------------------------------------------------------------------
#define QSTR 68
#define PSTR 68
#define FLASH_SMEM_FLOATS (128*QSTR*2 + 64*128 + 64*PSTR)
#define FLASH_SMEM_BYTES  (FLASH_SMEM_FLOATS * 4)

__global__ __launch_bounds__(256, 1)
void flash_kernel(const float* __restrict__ Qd, const float* __restrict__ Kd,
                  const float* __restrict__ Vt, float* __restrict__ Ctx)
{
    extern __shared__ float sm[];
    float* Qs = sm;                       // [128][QSTR]
    float* Ks = Qs + 128 * QSTR;          // [128][QSTR]
    float* Vs = Ks + 128 * QSTR;          // [64][128]
    float* Pt = Vs + 64 * 128;            // [64][PSTR]  (P transposed: [c][r])

    const int tid = threadIdx.x;
    const int tx  = tid & 15;
    const int ty  = tid >> 4;
    const int qt  = gridDim.x - 1 - blockIdx.x;   // big tiles scheduled first
    const int h   = blockIdx.y;
    const int kh  = h >> 2;
    const int qbase = qt * 64;

    const float* Qh = Qd + (size_t)h  * DH * T_SEQ;
    const float* Kh = Kd + (size_t)kh * DH * T_SEQ;

    // Load Q tile -> Qs[d][r], coalesced over t
    #pragma unroll
    for (int it = 0; it < 8; it++) {
        int idx = it * 256 + tid;
        int d   = idx >> 4;
        int rr  = (idx & 15) << 2;
        *(float4*)&Qs[d * QSTR + rr] = *(const float4*)&Qh[(size_t)d * T_SEQ + qbase + rr];
    }

    float m_i[4], l_i[4], Oc[4][8];
    #pragma unroll
    for (int jr = 0; jr < 4; jr++) {
        m_i[jr] = -1e30f;
        l_i[jr] = 0.f;
        #pragma unroll
        for (int c = 0; c < 8; c++) Oc[jr][c] = 0.f;
    }

    const float SCALE = 0.08838834764831843f;  // 1/sqrt(128)
    const int ntiles = qt + 1;

    for (int jt = 0; jt < ntiles; jt++) {
        const int kbase = jt * 64;
        __syncthreads();   // previous iter's smem reads done (also covers Q load)

        // K tile -> Ks[d][c]
        #pragma unroll
        for (int it = 0; it < 8; it++) {
            int idx = it * 256 + tid;
            int d   = idx >> 4;
            int rr  = (idx & 15) << 2;
            *(float4*)&Ks[d * QSTR + rr] = *(const float4*)&Kh[(size_t)d * T_SEQ + kbase + rr];
        }
        // V tile -> Vs[c][dd]
        #pragma unroll
        for (int it = 0; it < 8; it++) {
            int idx = it * 256 + tid;
            int r   = idx >> 5;
            int dd  = (idx & 31) << 2;
            *(float4*)&Vs[r * 128 + dd] =
                *(const float4*)&Vt[(size_t)(kbase + r) * DKV + kh * DH + dd];
        }
        __syncthreads();

        // S = Q @ K^T  (64x64, each thread 4x4)
        float S[4][4];
        #pragma unroll
        for (int a = 0; a < 4; a++)
            #pragma unroll
            for (int b = 0; b < 4; b++) S[a][b] = 0.f;

        #pragma unroll 8
        for (int d = 0; d < 128; d++) {
            float4 qa = *(const float4*)&Qs[d * QSTR + (ty << 2)];
            float4 ka = *(const float4*)&Ks[d * QSTR + (tx << 2)];
            float qr[4] = {qa.x, qa.y, qa.z, qa.w};
            float kr[4] = {ka.x, ka.y, ka.z, ka.w};
            #pragma unroll
            for (int a = 0; a < 4; a++)
                #pragma unroll
                for (int b = 0; b < 4; b++)
                    S[a][b] = fmaf(qr[a], kr[b], S[a][b]);
        }

        #pragma unroll
        for (int a = 0; a < 4; a++)
            #pragma unroll
            for (int b = 0; b < 4; b++) S[a][b] *= SCALE;

        if (jt == qt) {  // diagonal tile: mask c > r
            #pragma unroll
            for (int a = 0; a < 4; a++)
                #pragma unroll
                for (int b = 0; b < 4; b++)
                    if ((tx << 2) + b > (ty << 2) + a) S[a][b] = -1e30f;
        }

        // online softmax (row = 4*ty + jr; reduce across the 16 tx lanes)
        #pragma unroll
        for (int jr = 0; jr < 4; jr++) {
            float mx = fmaxf(fmaxf(S[jr][0], S[jr][1]), fmaxf(S[jr][2], S[jr][3]));
            #pragma unroll
            for (int o = 1; o < 16; o <<= 1)
                mx = fmaxf(mx, __shfl_xor_sync(0xffffffffu, mx, o));
            float mn = fmaxf(m_i[jr], mx);
            float sc = __expf(m_i[jr] - mn);
            m_i[jr] = mn;
            float rs = 0.f;
            #pragma unroll
            for (int jc = 0; jc < 4; jc++) {
                float p = __expf(S[jr][jc] - mn);
                S[jr][jc] = p;
                rs += p;
            }
            #pragma unroll
            for (int o = 1; o < 16; o <<= 1)
                rs += __shfl_xor_sync(0xffffffffu, rs, o);
            l_i[jr] = l_i[jr] * sc + rs;
            #pragma unroll
            for (int c = 0; c < 8; c++) Oc[jr][c] *= sc;
            #pragma unroll
            for (int jc = 0; jc < 4; jc++)
                Pt[((tx << 2) + jc) * PSTR + (ty << 2) + jr] = S[jr][jc];
        }
        __syncthreads();

        // O += P @ V
        #pragma unroll 4
        for (int c = 0; c < 64; c++) {
            float4 pa = *(const float4*)&Pt[c * PSTR + (ty << 2)];
            float4 v0 = *(const float4*)&Vs[c * 128 + (tx << 2)];
            float4 v1 = *(const float4*)&Vs[c * 128 + 64 + (tx << 2)];
            float pr[4] = {pa.x, pa.y, pa.z, pa.w};
            float vr[8] = {v0.x, v0.y, v0.z, v0.w, v1.x, v1.y, v1.z, v1.w};
            #pragma unroll
            for (int jr = 0; jr < 4; jr++)
                #pragma unroll
                for (int cc = 0; cc < 8; cc++)
                    Oc[jr][cc] = fmaf(pr[jr], vr[cc], Oc[jr][cc]);
        }
    }

    // epilogue: O /= l, write ctx [t][h*128+d]
    #pragma unroll
    for (int jr = 0; jr < 4; jr++) {
        float inv = 1.0f / l_i[jr];
        int row = qbase + (ty << 2) + jr;
        float* op = Ctx + (size_t)row * D_MODEL + h * DH;
        float4 o0 = make_float4(Oc[jr][0]*inv, Oc[jr][1]*inv, Oc[jr][2]*inv, Oc[jr][3]*inv);
        float4 o1 = make_float4(Oc[jr][4]*inv, Oc[jr][5]*inv, Oc[jr][6]*inv, Oc[jr][7]*inv);
        *(float4*)&op[(tx << 2)] = o0;
        *(float4*)&op[64 + (tx << 2)] = o1;
    }
}

// ---------------------------------------------------------------------------
// kernel_launch
// ---------------------------------------------------------------------------
extern "C" void kernel_launch(void* const* d_in, const int* in_sizes, int n_in,
                              void* d_out, int out_size)
{
    const float* x  = (const float*)d_in[0];
    const float* WQ = (const float*)d_in[1];
    const float* WK = (const float*)d_in[2];
    const float* WV = (const float*)d_in[3];
    const float* WO = (const float*)d_in[4];
    float* out = (float*)d_out;

    float *qp, *kp, *vp, *cp;
    cudaGetSymbolAddress((void**)&qp, g_Q);
    cudaGetSymbolAddress((void**)&kp, g_K);
    cudaGetSymbolAddress((void**)&vp, g_V);
    cudaGetSymbolAddress((void**)&cp, g_C);

    cudaFuncSetAttribute(flash_kernel,
                         cudaFuncAttributeMaxDynamicSharedMemorySize,
                         FLASH_SMEM_BYTES);

    // Projections: Q/K d-major (transposed epilogue), V row-major
    sgemm128<1><<<dim3(D_MODEL/128, T_SEQ/128), 256>>>(x, WQ, qp, T_SEQ, D_MODEL, D_MODEL);
    sgemm128<1><<<dim3(DKV/128,     T_SEQ/128), 256>>>(x, WK, kp, T_SEQ, DKV,     D_MODEL);
    sgemm128<0><<<dim3(DKV/128,     T_SEQ/128), 256>>>(x, WV, vp, T_SEQ, DKV,     D_MODEL);

    // RoPE on Q and K
    {
        int total = (NH + NKV) * (DH / 2) * T_SEQ;
        rope_kernel<<<(total + 255) / 256, 256>>>(qp, kp);
    }

    // Attention
    flash_kernel<<<dim3(T_SEQ/64, NH), 256, FLASH_SMEM_BYTES>>>(qp, kp, vp, cp);

    // Output projection
    sgemm128<0><<<dim3(D_MODEL/128, T_SEQ/128), 256>>>(cp, WO, out, T_SEQ, D_MODEL, D_MODEL);
}

// round 4
// speedup vs baseline: 3.3882x; 3.3882x over previous
#include <cuda_runtime.h>
#include <cuda_bf16.h>
#include <math.h>
#include <stdint.h>

// Problem constants
#define T_SEQ 4096
#define D_MODEL 2048
#define DH 128
#define NH 16
#define NKV 4
#define DKV 512   // NKV * DH

// ---------------------------------------------------------------------------
// Scratch (device globals — no allocations allowed)
// ---------------------------------------------------------------------------
__device__ float g_Q[(size_t)NH * T_SEQ * DH];       // [h][t][d]
__device__ float g_K[(size_t)NKV * DH * T_SEQ];      // [kh][d][t]
__device__ float g_V[(size_t)T_SEQ * DKV];           // [t][kh*128+d]
__device__ float g_C[(size_t)T_SEQ * D_MODEL];       // ctx [t][h*128+d] (tf32-rounded)
__device__ float g_Xr[(size_t)T_SEQ * D_MODEL];      // x rounded to tf32
__device__ float g_WQt[(size_t)D_MODEL * D_MODEL];   // W^T [n][k], tf32-rounded
__device__ float g_WKt[(size_t)D_MODEL * DKV];
__device__ float g_WVt[(size_t)D_MODEL * DKV];
__device__ float g_WOt[(size_t)D_MODEL * D_MODEL];

// ---------------------------------------------------------------------------
// Helpers (sm_80-compatible PTX only: mma.sync, cp.async, shfl)
// ---------------------------------------------------------------------------
__device__ __forceinline__ uint32_t smem_to_u32(const void* p) {
    uint32_t a;
    asm("{ .reg .u64 t; cvta.to.shared.u64 t, %1; cvt.u32.u64 %0, t; }"
        : "=r"(a) : "l"(p));
    return a;
}

__device__ __forceinline__ void cp_async16(uint32_t saddr, const void* g) {
    asm volatile("cp.async.cg.shared.global [%0], [%1], 16;" :: "r"(saddr), "l"(g));
}
#define CP_COMMIT() asm volatile("cp.async.commit_group;" ::: "memory")
#define CP_WAIT_0() asm volatile("cp.async.wait_group 0;" ::: "memory")
#define CP_WAIT_1() asm volatile("cp.async.wait_group 1;" ::: "memory")

__device__ __forceinline__ float to_tf32(float x) {
    uint32_t u;
    asm("cvt.rna.tf32.f32 %0, %1;" : "=r"(u) : "f"(x));
    return __uint_as_float(u);
}

// D += A(16x8, tf32 row) * B(8x8, tf32 col)  — fp32 accumulate
__device__ __forceinline__ void mma_tf32(float* d, const uint32_t* a, const uint32_t* b) {
    asm volatile(
        "mma.sync.aligned.m16n8k8.row.col.f32.tf32.tf32.f32 "
        "{%0,%1,%2,%3}, {%4,%5,%6,%7}, {%8,%9}, {%0,%1,%2,%3};"
        : "+f"(d[0]), "+f"(d[1]), "+f"(d[2]), "+f"(d[3])
        : "r"(a[0]), "r"(a[1]), "r"(a[2]), "r"(a[3]), "r"(b[0]), "r"(b[1]));
}

#define FU(x) __float_as_uint(x)

// ---------------------------------------------------------------------------
// GEMM (mma.sync tf32): C[M,N] = A[M,K] @ Bt[N,K]^T
//   128x128 tile, 256 thr, warp grid 2m x 4n (warp 64x32), K-tile 32,
//   3-stage cp.async pipeline, 1 barrier per K-tile.
//   cmode: 0 row-major C; 1 C[n*M+m] (d-major K); 2 head-block [h][t][d] (Q).
//   rnd:   round output to tf32 (for V).
// ---------------------------------------------------------------------------
#define GM_KT 32
#define GM_PAD 36
#define GM_STG 3
#define GM_SMEM (GM_STG * 128 * GM_PAD * 2 * 4)   // 110,592 B

__device__ __forceinline__ void gm_load_stage(
    const float* __restrict__ A, const float* __restrict__ Bt,
    uint32_t sA, uint32_t sB, int kt, int K, int tid)
{
    #pragma unroll
    for (int it = 0; it < 4; it++) {
        int idx = it * 256 + tid;
        int row = idx >> 3;
        int c   = idx & 7;
        uint32_t off = (uint32_t)(row * GM_PAD + c * 4) * 4;
        cp_async16(sA + off, A  + (size_t)row * K + kt * GM_KT + c * 4);
        cp_async16(sB + off, Bt + (size_t)row * K + kt * GM_KT + c * 4);
    }
}

__global__ __launch_bounds__(256)
void gemm_mma(const float* __restrict__ A, const float* __restrict__ Bt,
              float* __restrict__ C, int M, int N, int K, int cmode, int rnd)
{
    extern __shared__ __align__(16) float gsm[];
    float* As = gsm;                           // [3][128][GM_PAD]
    float* Bs = gsm + GM_STG * 128 * GM_PAD;   // [3][128][GM_PAD]

    const int tid  = threadIdx.x;
    const int w    = tid >> 5;
    const int lane = tid & 31;
    const int g    = lane >> 2;
    const int qd   = lane & 3;
    const int wm   = w & 1;
    const int wn   = w >> 1;
    const int m0   = blockIdx.y * 128;
    const int n0   = blockIdx.x * 128;
    const int NKT  = K / GM_KT;

    const float* Ab = A  + (size_t)m0 * K;
    const float* Bb = Bt + (size_t)n0 * K;
    const uint32_t sAu = smem_to_u32(As);
    const uint32_t sBu = smem_to_u32(Bs);
    const uint32_t stg_f = 128 * GM_PAD;          // floats per stage
    const uint32_t stg_b = stg_f * 4;             // bytes per stage

    float acc[4][4][4];
    #pragma unroll
    for (int mt = 0; mt < 4; mt++)
        #pragma unroll
        for (int nt = 0; nt < 4; nt++)
            #pragma unroll
            for (int e = 0; e < 4; e++) acc[mt][nt][e] = 0.f;

    // prologue: stages 0,1
    gm_load_stage(Ab, Bb, sAu, sBu, 0, K, tid); CP_COMMIT();
    gm_load_stage(Ab, Bb, sAu + stg_b, sBu + stg_b, 1, K, tid); CP_COMMIT();

    for (int kt = 0; kt < NKT; kt++) {
        CP_WAIT_1();
        __syncthreads();
        if (kt + 2 < NKT) {
            int s2 = (kt + 2) % GM_STG;
            gm_load_stage(Ab, Bb, sAu + s2 * stg_b, sBu + s2 * stg_b, kt + 2, K, tid);
            CP_COMMIT();
        }
        const float* Ac = As + (kt % GM_STG) * stg_f;
        const float* Bc = Bs + (kt % GM_STG) * stg_f;

        #pragma unroll
        for (int kk = 0; kk < GM_KT; kk += 8) {
            uint32_t a[4][4];
            #pragma unroll
            for (int mt = 0; mt < 4; mt++) {
                int r = 64 * wm + 16 * mt + g;
                a[mt][0] = FU(Ac[(r    ) * GM_PAD + kk + qd    ]);
                a[mt][1] = FU(Ac[(r + 8) * GM_PAD + kk + qd    ]);
                a[mt][2] = FU(Ac[(r    ) * GM_PAD + kk + qd + 4]);
                a[mt][3] = FU(Ac[(r + 8) * GM_PAD + kk + qd + 4]);
            }
            uint32_t b[4][2];
            #pragma unroll
            for (int nt = 0; nt < 4; nt++) {
                int n = 32 * wn + 8 * nt + g;
                b[nt][0] = FU(Bc[n * GM_PAD + kk + qd    ]);
                b[nt][1] = FU(Bc[n * GM_PAD + kk + qd + 4]);
            }
            #pragma unroll
            for (int mt = 0; mt < 4; mt++)
                #pragma unroll
                for (int nt = 0; nt < 4; nt++)
                    mma_tf32(acc[mt][nt], a[mt], b[nt]);
        }
    }

    // epilogue
    #pragma unroll
    for (int mt = 0; mt < 4; mt++) {
        #pragma unroll
        for (int nt = 0; nt < 4; nt++) {
            int r = m0 + 64 * wm + 16 * mt + g;
            int c = n0 + 32 * wn + 8 * nt + 2 * qd;
            #pragma unroll
            for (int hf = 0; hf < 2; hf++) {
                int rr = r + hf * 8;
                float v0 = acc[mt][nt][2 * hf + 0];
                float v1 = acc[mt][nt][2 * hf + 1];
                if (rnd) { v0 = to_tf32(v0); v1 = to_tf32(v1); }
                if (cmode == 0) {
                    *(float2*)&C[(size_t)rr * N + c] = make_float2(v0, v1);
                } else if (cmode == 1) {
                    C[(size_t)(c    ) * M + rr] = v0;
                    C[(size_t)(c + 1) * M + rr] = v1;
                } else {
                    size_t base = ((size_t)(c >> 7) * M + rr) * 128 + (c & 127);
                    *(float2*)&C[base] = make_float2(v0, v1);
                }
            }
        }
    }
}

// ---------------------------------------------------------------------------
// Weight transpose + tf32 rounding: Wt[n][k] = rna_tf32(W[k][n])
// ---------------------------------------------------------------------------
__global__ void transpose_rnd(const float* __restrict__ W, float* __restrict__ Wt,
                              int K, int N)
{
    __shared__ float t[32][33];
    int k0 = blockIdx.y * 32, n0 = blockIdx.x * 32;
    #pragma unroll
    for (int i = threadIdx.y; i < 32; i += 8)
        t[i][threadIdx.x] = W[(size_t)(k0 + i) * N + n0 + threadIdx.x];
    __syncthreads();
    #pragma unroll
    for (int i = threadIdx.y; i < 32; i += 8)
        Wt[(size_t)(n0 + i) * K + k0 + threadIdx.x] = to_tf32(t[threadIdx.x][i]);
}

__global__ void round_tf32_kernel(const float4* __restrict__ in, float4* __restrict__ out, int n4)
{
    int i = blockIdx.x * blockDim.x + threadIdx.x;
    if (i < n4) {
        float4 v = in[i];
        v.x = to_tf32(v.x); v.y = to_tf32(v.y);
        v.z = to_tf32(v.z); v.w = to_tf32(v.w);
        out[i] = v;
    }
}

// ---------------------------------------------------------------------------
// RoPE: Q [h][t][d] (float2 pairs), K [kh][d][t] (d-major). Rounds outputs
// to tf32 (RNA) so the attention MMAs see round-to-nearest operands.
// ---------------------------------------------------------------------------
#define ROPE_NQ (NH * T_SEQ * (DH / 2))
#define ROPE_NK (NKV * (DH / 2) * T_SEQ)

__global__ void rope_kernel(float* __restrict__ Q, float* __restrict__ Kd)
{
    int idx = blockIdx.x * blockDim.x + threadIdx.x;
    if (idx < ROPE_NQ) {
        int i = idx & 63;
        int t = (idx >> 6) & (T_SEQ - 1);
        int h = idx >> 18;
        float omega = (float)(1.0 / pow(10000.0, (double)(2 * i) / (double)DH));
        float ang = (float)t * omega;
        float s, c;
        sincosf(ang, &s, &c);
        float2* p = (float2*)&Q[(((size_t)h * T_SEQ + t) << 7) + 2 * i];
        float2 v = *p;
        *p = make_float2(to_tf32(v.x * c - v.y * s), to_tf32(v.x * s + v.y * c));
    } else if (idx < ROPE_NQ + ROPE_NK) {
        int j = idx - ROPE_NQ;
        int t = j & (T_SEQ - 1);
        int rest = j >> 12;
        int kh = rest >> 6;
        int i  = rest & 63;
        float omega = (float)(1.0 / pow(10000.0, (double)(2 * i) / (double)DH));
        float ang = (float)t * omega;
        float s, c;
        sincosf(ang, &s, &c);
        float* base = Kd + (size_t)(kh * DH + 2 * i) * T_SEQ + t;
        float x0 = base[0];
        float x1 = base[T_SEQ];
        base[0]     = to_tf32(x0 * c - x1 * s);
        base[T_SEQ] = to_tf32(x0 * s + x1 * c);
    }
}

// ---------------------------------------------------------------------------
// Flash attention on mma.sync tf32. q-tile 128, kv-tile 64, 256 thr (8 warps).
// Warp w owns rows 16w..16w+15 -> softmax warp-local (quad shfl).
// Smem: Qs[128][132] (q-major), Ks[2][128][72] (d-major, double buffered),
//       Vs[64][136], Ps[128][68]. K/V via cp.async overlapped with MMAs.
// ---------------------------------------------------------------------------
#define QPAD 132
#define KPAD 72
#define VPAD 136
#define PPAD 68
#define FL_SMEM ((128*QPAD + 2*128*KPAD + 64*VPAD + 128*PPAD) * 4)  // 210,944 B

__global__ __launch_bounds__(256, 1)
void flash_mma(const float* __restrict__ Qg, const float* __restrict__ Kd,
               const float* __restrict__ Vt, float* __restrict__ Ctx)
{
    extern __shared__ __align__(16) float sm[];
    float* Qs = sm;                         // [128][QPAD]
    float* Ks = Qs + 128 * QPAD;            // [2][128][KPAD]
    float* Vs = Ks + 2 * 128 * KPAD;        // [64][VPAD]
    float* Ps = Vs + 64 * VPAD;             // [128][PPAD]

    const int tid  = threadIdx.x;
    const int w    = tid >> 5;
    const int lane = tid & 31;
    const int g    = lane >> 2;
    const int qd   = lane & 3;
    const int qt   = gridDim.x - 1 - blockIdx.x;   // big tiles first
    const int h    = blockIdx.y;
    const int kh   = h >> 2;
    const int qbase = qt * 128;
    const int r0   = 16 * w + g;

    const float* Qh = Qg + (size_t)h * T_SEQ * DH;
    const float* Kh = Kd + (size_t)kh * DH * T_SEQ;
    const uint32_t ksu = smem_to_u32(Ks);
    const uint32_t vsu = smem_to_u32(Vs);

    // Q tile (sync loads; first loop barrier covers visibility)
    #pragma unroll
    for (int it = 0; it < 16; it++) {
        int idx = it * 256 + tid;
        int r = idx >> 5, c = (idx & 31) << 2;
        *(float4*)&Qs[r * QPAD + c] = *(const float4*)&Qh[(size_t)(qbase + r) * DH + c];
    }

    // prologue: K(0)
    #pragma unroll
    for (int it = 0; it < 8; it++) {
        int idx = it * 256 + tid;
        int d = idx >> 4, c = idx & 15;
        cp_async16(ksu + (uint32_t)(d * KPAD + c * 4) * 4,
                   Kh + (size_t)d * T_SEQ + c * 4);
    }
    CP_COMMIT();

    float m_i[2] = {-1e30f, -1e30f};
    float l_i[2] = {0.f, 0.f};
    float o[16][4];
    #pragma unroll
    for (int nt = 0; nt < 16; nt++)
        #pragma unroll
        for (int e = 0; e < 4; e++) o[nt][e] = 0.f;

    const float SCALE = 0.08838834764831843f;   // 1/sqrt(128)
    const int ntiles = 2 * qt + 2;

    for (int jt = 0; jt < ntiles; jt++) {
        const int kbase = jt * 64;
        const float* Kc = Ks + (jt & 1) * 128 * KPAD;

        CP_WAIT_0();        // K(jt) landed
        __syncthreads();    // visible to all; Vs free (prev PV done)

        // issue V(jt)
        #pragma unroll
        for (int it = 0; it < 8; it++) {
            int idx = it * 256 + tid;
            int r = idx >> 5, c = idx & 31;
            cp_async16(vsu + (uint32_t)(r * VPAD + c * 4) * 4,
                       Vt + (size_t)(kbase + r) * DKV + kh * DH + c * 4);
        }
        CP_COMMIT();

        // S = Q @ K^T  (warp rows r0, r0+8; full 64 kv)
        float s[8][4];
        #pragma unroll
        for (int nt = 0; nt < 8; nt++)
            #pragma unroll
            for (int e = 0; e < 4; e++) s[nt][e] = 0.f;

        #pragma unroll
        for (int kk = 0; kk < 16; kk++) {
            uint32_t a[4];
            a[0] = FU(Qs[(r0    ) * QPAD + 8 * kk + qd    ]);
            a[1] = FU(Qs[(r0 + 8) * QPAD + 8 * kk + qd    ]);
            a[2] = FU(Qs[(r0    ) * QPAD + 8 * kk + qd + 4]);
            a[3] = FU(Qs[(r0 + 8) * QPAD + 8 * kk + qd + 4]);
            #pragma unroll
            for (int nt = 0; nt < 8; nt++) {
                uint32_t b[2];
                b[0] = FU(Kc[(8 * kk + qd    ) * KPAD + nt * 8 + g]);
                b[1] = FU(Kc[(8 * kk + qd + 4) * KPAD + nt * 8 + g]);
                mma_tf32(s[nt], a, b);
            }
        }

        #pragma unroll
        for (int nt = 0; nt < 8; nt++)
            #pragma unroll
            for (int e = 0; e < 4; e++) s[nt][e] *= SCALE;

        if (jt >= 2 * qt) {   // diagonal region: mask col > row
            #pragma unroll
            for (int nt = 0; nt < 8; nt++)
                #pragma unroll
                for (int e = 0; e < 4; e++) {
                    int col = kbase + nt * 8 + 2 * qd + (e & 1);
                    int row = qbase + r0 + ((e >> 1) << 3);
                    if (col > row) s[nt][e] = -1e30f;
                }
        }

        // online softmax (rows r0: e0,e1; r0+8: e2,e3) — quad shfl reduce
        {
            float mx0 = -1e30f, mx1 = -1e30f;
            #pragma unroll
            for (int nt = 0; nt < 8; nt++) {
                mx0 = fmaxf(mx0, fmaxf(s[nt][0], s[nt][1]));
                mx1 = fmaxf(mx1, fmaxf(s[nt][2], s[nt][3]));
            }
            mx0 = fmaxf(mx0, __shfl_xor_sync(0xffffffffu, mx0, 1));
            mx0 = fmaxf(mx0, __shfl_xor_sync(0xffffffffu, mx0, 2));
            mx1 = fmaxf(mx1, __shfl_xor_sync(0xffffffffu, mx1, 1));
            mx1 = fmaxf(mx1, __shfl_xor_sync(0xffffffffu, mx1, 2));
            float mn0 = fmaxf(m_i[0], mx0);
            float mn1 = fmaxf(m_i[1], mx1);
            float sc0 = __expf(m_i[0] - mn0);
            float sc1 = __expf(m_i[1] - mn1);
            m_i[0] = mn0; m_i[1] = mn1;

            float rs0 = 0.f, rs1 = 0.f;
            #pragma unroll
            for (int nt = 0; nt < 8; nt++) {
                s[nt][0] = __expf(s[nt][0] - mn0);
                s[nt][1] = __expf(s[nt][1] - mn0);
                s[nt][2] = __expf(s[nt][2] - mn1);
                s[nt][3] = __expf(s[nt][3] - mn1);
                rs0 += s[nt][0] + s[nt][1];
                rs1 += s[nt][2] + s[nt][3];
            }
            rs0 += __shfl_xor_sync(0xffffffffu, rs0, 1);
            rs0 += __shfl_xor_sync(0xffffffffu, rs0, 2);
            rs1 += __shfl_xor_sync(0xffffffffu, rs1, 1);
            rs1 += __shfl_xor_sync(0xffffffffu, rs1, 2);
            l_i[0] = l_i[0] * sc0 + rs0;
            l_i[1] = l_i[1] * sc1 + rs1;

            #pragma unroll
            for (int nt = 0; nt < 16; nt++) {
                o[nt][0] *= sc0; o[nt][1] *= sc0;
                o[nt][2] *= sc1; o[nt][3] *= sc1;
            }
            // stage P (rounded) — warp-private rows
            #pragma unroll
            for (int nt = 0; nt < 8; nt++) {
                *(float2*)&Ps[(r0    ) * PPAD + nt * 8 + 2 * qd] =
                    make_float2(to_tf32(s[nt][0]), to_tf32(s[nt][1]));
                *(float2*)&Ps[(r0 + 8) * PPAD + nt * 8 + 2 * qd] =
                    make_float2(to_tf32(s[nt][2]), to_tf32(s[nt][3]));
            }
            __syncwarp();
        }

        CP_WAIT_0();        // V(jt) landed
        __syncthreads();    // visible to all warps

        // issue K(jt+1)
        if (jt + 1 < ntiles) {
            uint32_t kb2 = ksu + (uint32_t)(((jt + 1) & 1) * 128 * KPAD) * 4;
            #pragma unroll
            for (int it = 0; it < 8; it++) {
                int idx = it * 256 + tid;
                int d = idx >> 4, c = idx & 15;
                cp_async16(kb2 + (uint32_t)(d * KPAD + c * 4) * 4,
                           Kh + (size_t)d * T_SEQ + (kbase + 64) + c * 4);
            }
            CP_COMMIT();
        }

        // O += P @ V
        #pragma unroll
        for (int kk = 0; kk < 8; kk++) {
            uint32_t a[4];
            a[0] = FU(Ps[(r0    ) * PPAD + 8 * kk + qd    ]);
            a[1] = FU(Ps[(r0 + 8) * PPAD + 8 * kk + qd    ]);
            a[2] = FU(Ps[(r0    ) * PPAD + 8 * kk + qd + 4]);
            a[3] = FU(Ps[(r0 + 8) * PPAD + 8 * kk + qd + 4]);
            #pragma unroll
            for (int nt = 0; nt < 16; nt++) {
                uint32_t b[2];
                b[0] = FU(Vs[(8 * kk + qd    ) * VPAD + nt * 8 + g]);
                b[1] = FU(Vs[(8 * kk + qd + 4) * VPAD + nt * 8 + g]);
                mma_tf32(o[nt], a, b);
            }
        }
    }

    // epilogue: normalize, round to tf32 (feeds O-projection), write ctx
    float inv0 = 1.0f / l_i[0];
    float inv1 = 1.0f / l_i[1];
    #pragma unroll
    for (int nt = 0; nt < 16; nt++) {
        size_t b0 = (size_t)(qbase + r0    ) * D_MODEL + h * DH + nt * 8 + 2 * qd;
        size_t b1 = (size_t)(qbase + r0 + 8) * D_MODEL + h * DH + nt * 8 + 2 * qd;
        *(float2*)&Ctx[b0] = make_float2(to_tf32(o[nt][0] * inv0), to_tf32(o[nt][1] * inv0));
        *(float2*)&Ctx[b1] = make_float2(to_tf32(o[nt][2] * inv1), to_tf32(o[nt][3] * inv1));
    }
}

// ---------------------------------------------------------------------------
// kernel_launch
// ---------------------------------------------------------------------------
extern "C" void kernel_launch(void* const* d_in, const int* in_sizes, int n_in,
                              void* d_out, int out_size)
{
    const float* x  = (const float*)d_in[0];
    const float* WQ = (const float*)d_in[1];
    const float* WK = (const float*)d_in[2];
    const float* WV = (const float*)d_in[3];
    const float* WO = (const float*)d_in[4];
    float* out = (float*)d_out;

    float *qp, *kp, *vp, *cp, *xr, *wqt, *wkt, *wvt, *wot;
    cudaGetSymbolAddress((void**)&qp,  g_Q);
    cudaGetSymbolAddress((void**)&kp,  g_K);
    cudaGetSymbolAddress((void**)&vp,  g_V);
    cudaGetSymbolAddress((void**)&cp,  g_C);
    cudaGetSymbolAddress((void**)&xr,  g_Xr);
    cudaGetSymbolAddress((void**)&wqt, g_WQt);
    cudaGetSymbolAddress((void**)&wkt, g_WKt);
    cudaGetSymbolAddress((void**)&wvt, g_WVt);
    cudaGetSymbolAddress((void**)&wot, g_WOt);

    cudaFuncSetAttribute(flash_mma,
                         cudaFuncAttributeMaxDynamicSharedMemorySize, FL_SMEM);
    cudaFuncSetAttribute(gemm_mma,
                         cudaFuncAttributeMaxDynamicSharedMemorySize, GM_SMEM);

    // A-operand rounding (RNA) for the projections
    {
        int n4 = T_SEQ * D_MODEL / 4;
        round_tf32_kernel<<<(n4 + 255) / 256, 256>>>((const float4*)x, (float4*)xr, n4);
    }
    // Weight transposes to [N][K] with tf32 rounding
    transpose_rnd<<<dim3(D_MODEL/32, D_MODEL/32), dim3(32, 8)>>>(WQ, wqt, D_MODEL, D_MODEL);
    transpose_rnd<<<dim3(DKV/32,     D_MODEL/32), dim3(32, 8)>>>(WK, wkt, D_MODEL, DKV);
    transpose_rnd<<<dim3(DKV/32,     D_MODEL/32), dim3(32, 8)>>>(WV, wvt, D_MODEL, DKV);
    transpose_rnd<<<dim3(D_MODEL/32, D_MODEL/32), dim3(32, 8)>>>(WO, wot, D_MODEL, D_MODEL);

    // Projections (tensor cores): Q -> [h][t][d], K -> d-major, V row-major(rounded)
    gemm_mma<<<dim3(D_MODEL/128, T_SEQ/128), 256, GM_SMEM>>>(xr, wqt, qp, T_SEQ, D_MODEL, D_MODEL, 2, 0);
    gemm_mma<<<dim3(DKV/128,     T_SEQ/128), 256, GM_SMEM>>>(xr, wkt, kp, T_SEQ, DKV,     D_MODEL, 1, 0);
    gemm_mma<<<dim3(DKV/128,     T_SEQ/128), 256, GM_SMEM>>>(xr, wvt, vp, T_SEQ, DKV,     D_MODEL, 0, 1);

    // RoPE (rounds Q/K to tf32)
    {
        int total = ROPE_NQ + ROPE_NK;
        rope_kernel<<<(total + 255) / 256, 256>>>(qp, kp);
    }

    // Attention (tensor cores; writes tf32-rounded ctx)
    flash_mma<<<dim3(T_SEQ/128, NH), 256, FL_SMEM>>>(qp, kp, vp, cp);

    // Output projection
    gemm_mma<<<dim3(D_MODEL/128, T_SEQ/128), 256, GM_SMEM>>>(cp, wot, out, T_SEQ, D_MODEL, D_MODEL, 0, 0);
}

// round 5
// speedup vs baseline: 3.5445x; 1.0461x over previous
#include <cuda_runtime.h>
#include <cuda_bf16.h>
#include <math.h>
#include <stdint.h>

// Problem constants
#define T_SEQ 4096
#define D_MODEL 2048
#define DH 128
#define NH 16
#define NKV 4
#define DKV 512   // NKV * DH
#define NQKV 3072 // D_MODEL + 2*DKV

// ---------------------------------------------------------------------------
// Scratch (device globals — no allocations allowed)
// ---------------------------------------------------------------------------
__device__ float g_Q[(size_t)NH * T_SEQ * DH];       // [h][t][d]   (roped, tf32)
__device__ float g_K[(size_t)NKV * DH * T_SEQ];      // [kh][d][t]  (roped, tf32)
__device__ float g_V[(size_t)T_SEQ * DKV];           // [t][kh*128+d] (tf32)
__device__ float g_C[(size_t)T_SEQ * D_MODEL];       // ctx [t][h*128+d] (tf32)
__device__ float g_Xr[(size_t)T_SEQ * D_MODEL];      // x rounded to tf32
__device__ float g_Wqkv[(size_t)NQKV * D_MODEL];     // [WQ^T;WK^T;WV^T] [n][k] tf32
__device__ float g_WOt[(size_t)D_MODEL * D_MODEL];   // WO^T [n][k] tf32

// ---------------------------------------------------------------------------
// Helpers (sm_80-compatible PTX only: mma.sync, cp.async, shfl)
// ---------------------------------------------------------------------------
__device__ __forceinline__ uint32_t smem_to_u32(const void* p) {
    uint32_t a;
    asm("{ .reg .u64 t; cvta.to.shared.u64 t, %1; cvt.u32.u64 %0, t; }"
        : "=r"(a) : "l"(p));
    return a;
}

__device__ __forceinline__ void cp_async16(uint32_t saddr, const void* g) {
    asm volatile("cp.async.cg.shared.global [%0], [%1], 16;" :: "r"(saddr), "l"(g));
}
#define CP_COMMIT() asm volatile("cp.async.commit_group;" ::: "memory")
#define CP_WAIT_0() asm volatile("cp.async.wait_group 0;" ::: "memory")
#define CP_WAIT_1() asm volatile("cp.async.wait_group 1;" ::: "memory")

__device__ __forceinline__ float to_tf32(float x) {
    uint32_t u;
    asm("cvt.rna.tf32.f32 %0, %1;" : "=r"(u) : "f"(x));
    return __uint_as_float(u);
}

// D += A(16x8, tf32 row) * B(8x8, tf32 col)  — fp32 accumulate
__device__ __forceinline__ void mma_tf32(float* d, const uint32_t* a, const uint32_t* b) {
    asm volatile(
        "mma.sync.aligned.m16n8k8.row.col.f32.tf32.tf32.f32 "
        "{%0,%1,%2,%3}, {%4,%5,%6,%7}, {%8,%9}, {%0,%1,%2,%3};"
        : "+f"(d[0]), "+f"(d[1]), "+f"(d[2]), "+f"(d[3])
        : "r"(a[0]), "r"(a[1]), "r"(a[2]), "r"(a[3]), "r"(b[0]), "r"(b[1]));
}

#define FU(x) __float_as_uint(x)

// ---------------------------------------------------------------------------
// GEMM (mma.sync tf32): C[M,N] = A[M,K] @ Bt[N,K]^T
//   128x128 tile, 256 thr, warp grid 2m x 4n (warp 64x32), K-tile 32,
//   3-stage cp.async pipeline.
//   cmode 0: row-major C (O-projection).
//   cmode 3: fused QKV epilogue with RoPE:
//     n in [0,2048):     Q head-block [h][t][d], rope+tf32
//     n in [2048,2560):  K d-major [kh][d][t],   rope+tf32
//     n in [2560,3072):  V row-major [t][512],   tf32
// ---------------------------------------------------------------------------
#define GM_KT 32
#define GM_PAD 36
#define GM_STG 3
#define GM_SMEM (GM_STG * 128 * GM_PAD * 2 * 4)   // 110,592 B

__device__ __forceinline__ void gm_load_stage(
    const float* __restrict__ A, const float* __restrict__ Bt,
    uint32_t sA, uint32_t sB, int kt, int K, int tid)
{
    #pragma unroll
    for (int it = 0; it < 4; it++) {
        int idx = it * 256 + tid;
        int row = idx >> 3;
        int c   = idx & 7;
        uint32_t off = (uint32_t)(row * GM_PAD + c * 4) * 4;
        cp_async16(sA + off, A  + (size_t)row * K + kt * GM_KT + c * 4);
        cp_async16(sB + off, Bt + (size_t)row * K + kt * GM_KT + c * 4);
    }
}

__global__ __launch_bounds__(256)
void gemm_mma(const float* __restrict__ A, const float* __restrict__ Bt,
              float* __restrict__ C, int M, int N, int K, int cmode)
{
    extern __shared__ __align__(16) float gsm[];
    float* As = gsm;                           // [3][128][GM_PAD]
    float* Bs = gsm + GM_STG * 128 * GM_PAD;   // [3][128][GM_PAD]

    const int tid  = threadIdx.x;
    const int w    = tid >> 5;
    const int lane = tid & 31;
    const int g    = lane >> 2;
    const int qd   = lane & 3;
    const int wm   = w & 1;
    const int wn   = w >> 1;
    const int m0   = blockIdx.y * 128;
    const int n0   = blockIdx.x * 128;
    const int NKT  = K / GM_KT;

    const float* Ab = A  + (size_t)m0 * K;
    const float* Bb = Bt + (size_t)n0 * K;
    const uint32_t sAu = smem_to_u32(As);
    const uint32_t sBu = smem_to_u32(Bs);
    const uint32_t stg_f = 128 * GM_PAD;
    const uint32_t stg_b = stg_f * 4;

    float acc[4][4][4];
    #pragma unroll
    for (int mt = 0; mt < 4; mt++)
        #pragma unroll
        for (int nt = 0; nt < 4; nt++)
            #pragma unroll
            for (int e = 0; e < 4; e++) acc[mt][nt][e] = 0.f;

    gm_load_stage(Ab, Bb, sAu, sBu, 0, K, tid); CP_COMMIT();
    gm_load_stage(Ab, Bb, sAu + stg_b, sBu + stg_b, 1, K, tid); CP_COMMIT();

    for (int kt = 0; kt < NKT; kt++) {
        CP_WAIT_1();
        __syncthreads();
        if (kt + 2 < NKT) {
            int s2 = (kt + 2) % GM_STG;
            gm_load_stage(Ab, Bb, sAu + s2 * stg_b, sBu + s2 * stg_b, kt + 2, K, tid);
            CP_COMMIT();
        }
        const float* Ac = As + (kt % GM_STG) * stg_f;
        const float* Bc = Bs + (kt % GM_STG) * stg_f;

        #pragma unroll
        for (int kk = 0; kk < GM_KT; kk += 8) {
            uint32_t a[4][4];
            #pragma unroll
            for (int mt = 0; mt < 4; mt++) {
                int r = 64 * wm + 16 * mt + g;
                a[mt][0] = FU(Ac[(r    ) * GM_PAD + kk + qd    ]);
                a[mt][1] = FU(Ac[(r + 8) * GM_PAD + kk + qd    ]);
                a[mt][2] = FU(Ac[(r    ) * GM_PAD + kk + qd + 4]);
                a[mt][3] = FU(Ac[(r + 8) * GM_PAD + kk + qd + 4]);
            }
            uint32_t b[4][2];
            #pragma unroll
            for (int nt = 0; nt < 4; nt++) {
                int n = 32 * wn + 8 * nt + g;
                b[nt][0] = FU(Bc[n * GM_PAD + kk + qd    ]);
                b[nt][1] = FU(Bc[n * GM_PAD + kk + qd + 4]);
            }
            #pragma unroll
            for (int mt = 0; mt < 4; mt++)
                #pragma unroll
                for (int nt = 0; nt < 4; nt++)
                    mma_tf32(acc[mt][nt], a[mt], b[nt]);
        }
    }

    // epilogue
    #pragma unroll
    for (int mt = 0; mt < 4; mt++) {
        #pragma unroll
        for (int nt = 0; nt < 4; nt++) {
            int r = m0 + 64 * wm + 16 * mt + g;
            int c = n0 + 32 * wn + 8 * nt + 2 * qd;
            if (cmode == 0) {
                #pragma unroll
                for (int hf = 0; hf < 2; hf++) {
                    int rr = r + hf * 8;
                    *(float2*)&C[(size_t)rr * N + c] =
                        make_float2(acc[mt][nt][2*hf], acc[mt][nt][2*hf+1]);
                }
            } else if (c < D_MODEL) {
                // Q with RoPE -> g_Q[h][t][d]
                int i = (c & 127) >> 1;
                float omega = (float)(1.0 / pow(10000.0, (double)(2 * i) / (double)DH));
                #pragma unroll
                for (int hf = 0; hf < 2; hf++) {
                    int rr = r + hf * 8;
                    float s, co;
                    sincosf((float)rr * omega, &s, &co);
                    float v0 = acc[mt][nt][2*hf], v1 = acc[mt][nt][2*hf+1];
                    size_t base = ((size_t)(c >> 7) * T_SEQ + rr) * 128 + (c & 127);
                    *(float2*)&g_Q[base] =
                        make_float2(to_tf32(v0 * co - v1 * s), to_tf32(v0 * s + v1 * co));
                }
            } else if (c < D_MODEL + DKV) {
                // K with RoPE -> g_K[kh][d][t] (d-major)
                int d  = c - D_MODEL;
                int kh = d >> 7;
                int dd = d & 127;
                int i  = dd >> 1;
                float omega = (float)(1.0 / pow(10000.0, (double)(2 * i) / (double)DH));
                #pragma unroll
                for (int hf = 0; hf < 2; hf++) {
                    int rr = r + hf * 8;
                    float s, co;
                    sincosf((float)rr * omega, &s, &co);
                    float v0 = acc[mt][nt][2*hf], v1 = acc[mt][nt][2*hf+1];
                    size_t base = ((size_t)kh * DH + dd) * T_SEQ + rr;
                    g_K[base]         = to_tf32(v0 * co - v1 * s);
                    g_K[base + T_SEQ] = to_tf32(v0 * s + v1 * co);
                }
            } else {
                // V -> g_V[t][512], tf32-rounded
                int d = c - (D_MODEL + DKV);
                #pragma unroll
                for (int hf = 0; hf < 2; hf++) {
                    int rr = r + hf * 8;
                    *(float2*)&g_V[(size_t)rr * DKV + d] =
                        make_float2(to_tf32(acc[mt][nt][2*hf]), to_tf32(acc[mt][nt][2*hf+1]));
                }
            }
        }
    }
}

// ---------------------------------------------------------------------------
// Batched weight transpose + tf32 rounding: one launch for WQ/WK/WV/WO.
// z=0: WQ -> g_Wqkv rows [0,2048);  z=1: WK -> rows [2048,2560);
// z=2: WV -> rows [2560,3072);      z=3: WO -> g_WOt.
// ---------------------------------------------------------------------------
__global__ void transpose_rnd4(const float* __restrict__ WQ, const float* __restrict__ WK,
                               const float* __restrict__ WV, const float* __restrict__ WO)
{
    __shared__ float t[32][33];
    int z = blockIdx.z;
    const float* src;
    float* dst;
    int N;
    if (z == 0)      { src = WQ; dst = g_Wqkv;                              N = D_MODEL; }
    else if (z == 1) { src = WK; dst = g_Wqkv + (size_t)D_MODEL * D_MODEL;  N = DKV; }
    else if (z == 2) { src = WV; dst = g_Wqkv + (size_t)(D_MODEL + DKV) * D_MODEL; N = DKV; }
    else             { src = WO; dst = g_WOt;                               N = D_MODEL; }

    int n0 = blockIdx.x * 32;
    if (n0 >= N) return;
    int k0 = blockIdx.y * 32;
    #pragma unroll
    for (int i = threadIdx.y; i < 32; i += 8)
        t[i][threadIdx.x] = src[(size_t)(k0 + i) * N + n0 + threadIdx.x];
    __syncthreads();
    #pragma unroll
    for (int i = threadIdx.y; i < 32; i += 8)
        dst[(size_t)(n0 + i) * D_MODEL + k0 + threadIdx.x] = to_tf32(t[threadIdx.x][i]);
}

__global__ void round_tf32_kernel(const float4* __restrict__ in, float4* __restrict__ out, int n4)
{
    int i = blockIdx.x * blockDim.x + threadIdx.x;
    if (i < n4) {
        float4 v = in[i];
        v.x = to_tf32(v.x); v.y = to_tf32(v.y);
        v.z = to_tf32(v.z); v.w = to_tf32(v.w);
        out[i] = v;
    }
}

// ---------------------------------------------------------------------------
// Flash attention on mma.sync tf32. q-tile 128, kv-tile 64, 256 thr (8 warps).
// Warp w owns rows 16w..16w+15 -> softmax warp-local (quad shfl).
// Q fragments cached in registers (loaded once); the Qs smem region is then
// reused as the second V buffer. K and V double-buffered, prefetched one full
// kv-tile ahead; ONE __syncthreads per kv-tile.
// ---------------------------------------------------------------------------
#define QPAD 132
#define KPAD 72
#define VPAD 136
#define PPAD 68
#define FL_SMEM ((128*QPAD + 2*128*KPAD + 64*VPAD + 128*PPAD) * 4)  // 210,944 B

__global__ __launch_bounds__(256, 1)
void flash_mma(const float* __restrict__ Qg, const float* __restrict__ Kd,
               const float* __restrict__ Vt, float* __restrict__ Ctx)
{
    extern __shared__ __align__(16) float sm[];
    float* Qs  = sm;                        // [128][QPAD] -> later V buffer 1
    float* Ks  = Qs + 128 * QPAD;           // [2][128][KPAD]
    float* Vs0 = Ks + 2 * 128 * KPAD;       // [64][VPAD]  (V buffer 0)
    float* Ps  = Vs0 + 64 * VPAD;           // [128][PPAD]

    const int tid  = threadIdx.x;
    const int w    = tid >> 5;
    const int lane = tid & 31;
    const int g    = lane >> 2;
    const int qd   = lane & 3;
    const int qt   = gridDim.x - 1 - blockIdx.x;   // big tiles first
    const int h    = blockIdx.y;
    const int kh   = h >> 2;
    const int qbase = qt * 128;
    const int r0   = 16 * w + g;

    const float* Qh = Qg + (size_t)h * T_SEQ * DH;
    const float* Kh = Kd + (size_t)kh * DH * T_SEQ;
    const uint32_t ksu = smem_to_u32(Ks);
    const uint32_t v0u = smem_to_u32(Vs0);
    const uint32_t v1u = smem_to_u32(Qs);   // V buffer 1 aliases Qs

    const int ntiles = 2 * qt + 2;

    // prologue: issue K(0) and V(0) first (latency overlap with Q staging)
    #pragma unroll
    for (int it = 0; it < 8; it++) {
        int idx = it * 256 + tid;
        int d = idx >> 4, c = idx & 15;
        cp_async16(ksu + (uint32_t)(d * KPAD + c * 4) * 4,
                   Kh + (size_t)d * T_SEQ + c * 4);
    }
    CP_COMMIT();
    #pragma unroll
    for (int it = 0; it < 8; it++) {
        int idx = it * 256 + tid;
        int r = idx >> 5, c = idx & 31;
        cp_async16(v0u + (uint32_t)(r * VPAD + c * 4) * 4,
                   Vt + (size_t)r * DKV + kh * DH + c * 4);
    }
    CP_COMMIT();

    // stage Q tile in smem, then preload fragments into registers
    #pragma unroll
    for (int it = 0; it < 16; it++) {
        int idx = it * 256 + tid;
        int r = idx >> 5, c = (idx & 31) << 2;
        *(float4*)&Qs[r * QPAD + c] = *(const float4*)&Qh[(size_t)(qbase + r) * DH + c];
    }
    __syncthreads();

    uint32_t qf[16][4];
    #pragma unroll
    for (int kk = 0; kk < 16; kk++) {
        qf[kk][0] = FU(Qs[(r0    ) * QPAD + 8 * kk + qd    ]);
        qf[kk][1] = FU(Qs[(r0 + 8) * QPAD + 8 * kk + qd    ]);
        qf[kk][2] = FU(Qs[(r0    ) * QPAD + 8 * kk + qd + 4]);
        qf[kk][3] = FU(Qs[(r0 + 8) * QPAD + 8 * kk + qd + 4]);
    }

    float m_i[2] = {-1e30f, -1e30f};
    float l_i[2] = {0.f, 0.f};
    float o[16][4];
    #pragma unroll
    for (int nt = 0; nt < 16; nt++)
        #pragma unroll
        for (int e = 0; e < 4; e++) o[nt][e] = 0.f;

    const float SCALE = 0.08838834764831843f;   // 1/sqrt(128)

    for (int jt = 0; jt < ntiles; jt++) {
        CP_WAIT_0();        // K(jt), V(jt) landed
        __syncthreads();    // visible; jt-1 buffers fully consumed by all warps

        // prefetch K(jt+1), V(jt+1) into the other buffers
        if (jt + 1 < ntiles) {
            const int kb2 = (jt + 1) * 64;
            uint32_t kdst = ksu + (uint32_t)(((jt + 1) & 1) * 128 * KPAD) * 4;
            #pragma unroll
            for (int it = 0; it < 8; it++) {
                int idx = it * 256 + tid;
                int d = idx >> 4, c = idx & 15;
                cp_async16(kdst + (uint32_t)(d * KPAD + c * 4) * 4,
                           Kh + (size_t)d * T_SEQ + kb2 + c * 4);
            }
            CP_COMMIT();
            uint32_t vdst = ((jt + 1) & 1) ? v1u : v0u;
            #pragma unroll
            for (int it = 0; it < 8; it++) {
                int idx = it * 256 + tid;
                int r = idx >> 5, c = idx & 31;
                cp_async16(vdst + (uint32_t)(r * VPAD + c * 4) * 4,
                           Vt + (size_t)(kb2 + r) * DKV + kh * DH + c * 4);
            }
            CP_COMMIT();
        }

        const int kbase = jt * 64;
        const float* Kc = Ks + (jt & 1) * 128 * KPAD;
        const float* Vc = (jt & 1) ? Qs : Vs0;

        // S = Q @ K^T
        float s[8][4];
        #pragma unroll
        for (int nt = 0; nt < 8; nt++)
            #pragma unroll
            for (int e = 0; e < 4; e++) s[nt][e] = 0.f;

        #pragma unroll
        for (int kk = 0; kk < 16; kk++) {
            #pragma unroll
            for (int nt = 0; nt < 8; nt++) {
                uint32_t b[2];
                b[0] = FU(Kc[(8 * kk + qd    ) * KPAD + nt * 8 + g]);
                b[1] = FU(Kc[(8 * kk + qd + 4) * KPAD + nt * 8 + g]);
                mma_tf32(s[nt], qf[kk], b);
            }
        }

        #pragma unroll
        for (int nt = 0; nt < 8; nt++)
            #pragma unroll
            for (int e = 0; e < 4; e++) s[nt][e] *= SCALE;

        if (jt >= 2 * qt) {   // diagonal region: mask col > row
            #pragma unroll
            for (int nt = 0; nt < 8; nt++)
                #pragma unroll
                for (int e = 0; e < 4; e++) {
                    int col = kbase + nt * 8 + 2 * qd + (e & 1);
                    int row = qbase + r0 + ((e >> 1) << 3);
                    if (col > row) s[nt][e] = -1e30f;
                }
        }

        // online softmax (rows r0: e0,e1; r0+8: e2,e3) — quad shfl reduce
        float mx0 = -1e30f, mx1 = -1e30f;
        #pragma unroll
        for (int nt = 0; nt < 8; nt++) {
            mx0 = fmaxf(mx0, fmaxf(s[nt][0], s[nt][1]));
            mx1 = fmaxf(mx1, fmaxf(s[nt][2], s[nt][3]));
        }
        mx0 = fmaxf(mx0, __shfl_xor_sync(0xffffffffu, mx0, 1));
        mx0 = fmaxf(mx0, __shfl_xor_sync(0xffffffffu, mx0, 2));
        mx1 = fmaxf(mx1, __shfl_xor_sync(0xffffffffu, mx1, 1));
        mx1 = fmaxf(mx1, __shfl_xor_sync(0xffffffffu, mx1, 2));
        float mn0 = fmaxf(m_i[0], mx0);
        float mn1 = fmaxf(m_i[1], mx1);
        float sc0 = __expf(m_i[0] - mn0);
        float sc1 = __expf(m_i[1] - mn1);
        m_i[0] = mn0; m_i[1] = mn1;

        float rs0 = 0.f, rs1 = 0.f;
        #pragma unroll
        for (int nt = 0; nt < 8; nt++) {
            s[nt][0] = __expf(s[nt][0] - mn0);
            s[nt][1] = __expf(s[nt][1] - mn0);
            s[nt][2] = __expf(s[nt][2] - mn1);
            s[nt][3] = __expf(s[nt][3] - mn1);
            rs0 += s[nt][0] + s[nt][1];
            rs1 += s[nt][2] + s[nt][3];
        }
        rs0 += __shfl_xor_sync(0xffffffffu, rs0, 1);
        rs0 += __shfl_xor_sync(0xffffffffu, rs0, 2);
        rs1 += __shfl_xor_sync(0xffffffffu, rs1, 1);
        rs1 += __shfl_xor_sync(0xffffffffu, rs1, 2);
        l_i[0] = l_i[0] * sc0 + rs0;
        l_i[1] = l_i[1] * sc1 + rs1;

        #pragma unroll
        for (int nt = 0; nt < 16; nt++) {
            o[nt][0] *= sc0; o[nt][1] *= sc0;
            o[nt][2] *= sc1; o[nt][3] *= sc1;
        }
        // stage P (rounded) — warp-private rows, syncwarp suffices
        #pragma unroll
        for (int nt = 0; nt < 8; nt++) {
            *(float2*)&Ps[(r0    ) * PPAD + nt * 8 + 2 * qd] =
                make_float2(to_tf32(s[nt][0]), to_tf32(s[nt][1]));
            *(float2*)&Ps[(r0 + 8) * PPAD + nt * 8 + 2 * qd] =
                make_float2(to_tf32(s[nt][2]), to_tf32(s[nt][3]));
        }
        __syncwarp();

        // O += P @ V   (V already resident — prefetched last iteration)
        #pragma unroll
        for (int kk = 0; kk < 8; kk++) {
            uint32_t a[4];
            a[0] = FU(Ps[(r0    ) * PPAD + 8 * kk + qd    ]);
            a[1] = FU(Ps[(r0 + 8) * PPAD + 8 * kk + qd    ]);
            a[2] = FU(Ps[(r0    ) * PPAD + 8 * kk + qd + 4]);
            a[3] = FU(Ps[(r0 + 8) * PPAD + 8 * kk + qd + 4]);
            #pragma unroll
            for (int nt = 0; nt < 16; nt++) {
                uint32_t b[2];
                b[0] = FU(Vc[(8 * kk + qd    ) * VPAD + nt * 8 + g]);
                b[1] = FU(Vc[(8 * kk + qd + 4) * VPAD + nt * 8 + g]);
                mma_tf32(o[nt], a, b);
            }
        }
    }

    // epilogue: normalize, round to tf32 (feeds O-projection), write ctx
    float inv0 = 1.0f / l_i[0];
    float inv1 = 1.0f / l_i[1];
    #pragma unroll
    for (int nt = 0; nt < 16; nt++) {
        size_t b0 = (size_t)(qbase + r0    ) * D_MODEL + h * DH + nt * 8 + 2 * qd;
        size_t b1 = (size_t)(qbase + r0 + 8) * D_MODEL + h * DH + nt * 8 + 2 * qd;
        *(float2*)&Ctx[b0] = make_float2(to_tf32(o[nt][0] * inv0), to_tf32(o[nt][1] * inv0));
        *(float2*)&Ctx[b1] = make_float2(to_tf32(o[nt][2] * inv1), to_tf32(o[nt][3] * inv1));
    }
}

// ---------------------------------------------------------------------------
// kernel_launch
// ---------------------------------------------------------------------------
extern "C" void kernel_launch(void* const* d_in, const int* in_sizes, int n_in,
                              void* d_out, int out_size)
{
    const float* x  = (const float*)d_in[0];
    const float* WQ = (const float*)d_in[1];
    const float* WK = (const float*)d_in[2];
    const float* WV = (const float*)d_in[3];
    const float* WO = (const float*)d_in[4];
    float* out = (float*)d_out;

    float *qp, *kp, *vp, *cp, *xr, *wqkv, *wot;
    cudaGetSymbolAddress((void**)&qp,   g_Q);
    cudaGetSymbolAddress((void**)&kp,   g_K);
    cudaGetSymbolAddress((void**)&vp,   g_V);
    cudaGetSymbolAddress((void**)&cp,   g_C);
    cudaGetSymbolAddress((void**)&xr,   g_Xr);
    cudaGetSymbolAddress((void**)&wqkv, g_Wqkv);
    cudaGetSymbolAddress((void**)&wot,  g_WOt);

    cudaFuncSetAttribute(flash_mma,
                         cudaFuncAttributeMaxDynamicSharedMemorySize, FL_SMEM);
    cudaFuncSetAttribute(gemm_mma,
                         cudaFuncAttributeMaxDynamicSharedMemorySize, GM_SMEM);

    // 1) round x to tf32 (RNA)
    {
        int n4 = T_SEQ * D_MODEL / 4;
        round_tf32_kernel<<<(n4 + 255) / 256, 256>>>((const float4*)x, (float4*)xr, n4);
    }
    // 2) all weight transposes in one launch
    transpose_rnd4<<<dim3(64, 64, 4), dim3(32, 8)>>>(WQ, WK, WV, WO);

    // 3) fused QKV projection (epilogue applies RoPE + layouts)
    gemm_mma<<<dim3(NQKV/128, T_SEQ/128), 256, GM_SMEM>>>(xr, wqkv, nullptr,
                                                          T_SEQ, NQKV, D_MODEL, 3);

    // 4) attention (tensor cores; writes tf32-rounded ctx)
    flash_mma<<<dim3(T_SEQ/128, NH), 256, FL_SMEM>>>(qp, kp, vp, cp);

    // 5) output projection
    gemm_mma<<<dim3(D_MODEL/128, T_SEQ/128), 256, GM_SMEM>>>(cp, wot, out,
                                                             T_SEQ, D_MODEL, D_MODEL, 0);
}